// round 14
// baseline (speedup 1.0000x reference)
#include <cuda_runtime.h>
#include <cstdint>

typedef unsigned long long u64;

#define T_STEPS 256
#define BATCH   8192
#define DEPTH   16           // ring slots (steps); commit granularity = 4 steps

__device__ __forceinline__ void ffma2(u64& acc, u64 a, u64 b) {
    asm("fma.rn.f32x2 %0, %1, %2, %0;" : "+l"(acc) : "l"(a), "l"(b));
}
__device__ __forceinline__ u64 fadd2(u64 a, u64 b) {
    u64 d; asm("add.rn.f32x2 %0, %1, %2;" : "=l"(d) : "l"(a), "l"(b)); return d;
}
__device__ __forceinline__ u64 pack2(float lo, float hi) {
    u64 v; asm("mov.b64 %0, {%1, %2};" : "=l"(v) : "f"(lo), "f"(hi)); return v;
}
__device__ __forceinline__ float2 unpack2(u64 v) {
    float2 r; asm("mov.b64 {%0, %1}, %2;" : "=f"(r.x), "=f"(r.y) : "l"(v)); return r;
}
__device__ __forceinline__ unsigned smem_u32(const void* p) {
    unsigned a;
    asm("{ .reg .u64 t; cvta.to.shared.u64 t, %1; cvt.u32.u64 %0, t; }" : "=r"(a) : "l"(p));
    return a;
}
__device__ __forceinline__ void cp_async16(unsigned dst, const void* src) {
    asm volatile("cp.async.ca.shared.global [%0], [%1], 16;" :: "r"(dst), "l"(src));
}
__device__ __forceinline__ void cp_commit() {
    asm volatile("cp.async.commit_group;" ::: "memory");
}
__device__ __forceinline__ void cp_wait3() {
    asm volatile("cp.async.wait_group 3;" ::: "memory");
}

// One warp = one batch element. Lane j<28 owns L1 neuron j; lane j<14 owns L2
// neuron j. Spikes via ballot; W2/W3 sums via smem LUTs (7-bit mask groups).
// 4 steps per commit/wait/sync block. Block body is LAYER-PHASED: 4 GEMMs,
// then LIF1 chain x4 (collect masks), then ALL 16 LUT2 loads (independent,
// latencies overlap), then LIF2 chain x4, then L3 loads + LIF3 x4.
// NOTE: all arithmetic expressions / add orders are identical to the proven
// 344.8us kernel — the GEMM 4-accumulator order and the LUT sum order are
// part of the correctness contract (spike flips under reassociation).
__global__ __launch_bounds__(256, 2)
void snn_all(const float* __restrict__ x,
             const float* __restrict__ W1, const float* __restrict__ b1,
             const float* __restrict__ W2, const float* __restrict__ b2,
             const float* __restrict__ W3, const float* __restrict__ b3,
             float* __restrict__ out)
{
    __shared__ __align__(16) u64 xring[8][DEPTH][32];   // 32 KB
    __shared__ float LUT2[4][128][16];                  // 32 KB (j padded 14->16)
    __shared__ float L3s[2][128];                       // 1 KB

    const int tid = threadIdx.x;

    // ---- build LUTs: LUT2[g][m][j] = sum_{k: m bit k} W2[j, 7g+k] ----
    for (int e = tid; e < 512; e += 256) {
        const int g = e >> 7, m = e & 127;
        #pragma unroll
        for (int j = 0; j < 16; j++) {
            float s = 0.0f;
            if (j < 14) {
                #pragma unroll
                for (int k = 0; k < 7; k++)
                    if (m & (1 << k)) s += W2[j * 28 + 7 * g + k];
            }
            LUT2[g][m][j] = s;
        }
    }
    {
        const int g = tid >> 7, m = tid & 127;
        float s = 0.0f;
        #pragma unroll
        for (int k = 0; k < 7; k++)
            if (m & (1 << k)) s += W3[7 * g + k];
        L3s[g][m] = s;
    }

    const int lane = tid & 31;
    const int w    = tid >> 5;
    const int b    = blockIdx.x * 8 + w;
    const int j1   = (lane < 28) ? lane : 27;
    const int j2   = (lane < 14) ? lane : 13;

    // ---- W1 row in registers (packed f32x2) ----
    u64 w1r[32];
    {
        const float4* wp = (const float4*)(W1 + j1 * 64);
        #pragma unroll
        for (int k = 0; k < 16; k++) {
            float4 v = wp[k];
            w1r[2*k]   = pack2(v.x, v.y);
            w1r[2*k+1] = pack2(v.z, v.w);
        }
    }
    const float b1j = b1[j1];
    const float b2j = b2[j2];
    const float b3v = b3[0];

    __syncthreads();   // LUTs ready

    // ---- cp.async ring: block of 4 steps = 1KB = 2 x 512B instructions.
    const int lhi = lane >> 4;          // which slot of the pair
    const int llo = lane & 15;          // 16B chunk within a 256B slot
    const float* xg2 = x + (size_t)b * 64 + llo * 4;
    const size_t tstride = (size_t)BATCH * 64;
    const unsigned ringq = smem_u32(&xring[w][0][0]) + (unsigned)(llo * 16);

    #define PRODUCE(tt) do {                                                    \
        const int sb_ = (tt) & (DEPTH - 1);                                     \
        cp_async16(ringq + (unsigned)((sb_ + lhi) * 256),                       \
                   xg2 + (size_t)((tt) + lhi) * tstride);                       \
        cp_async16(ringq + (unsigned)((sb_ + 2 + lhi) * 256),                   \
                   xg2 + (size_t)((tt) + 2 + lhi) * tstride);                   \
        cp_commit();                                                            \
    } while (0)

    PRODUCE(0); PRODUCE(4); PRODUCE(8);

    float m1 = 0.0f, m2 = 0.0f, m3 = 0.0f;

    // layer-1 dot product from ring slot s — EXACT 4-accumulator order
    #define GEMM(s, cur1) do {                                                  \
        const ulonglong2* xv = (const ulonglong2*)&xring[w][(s)][0];            \
        u64 a0 = pack2(b1j, 0.0f), a1 = 0ull, a2 = 0ull, a3 = 0ull;             \
        _Pragma("unroll")                                                       \
        for (int k = 0; k < 8; k++) {                                           \
            ulonglong2 p = xv[2*k];                                             \
            ulonglong2 q = xv[2*k+1];                                           \
            ffma2(a0, p.x, w1r[4*k]);                                           \
            ffma2(a1, p.y, w1r[4*k+1]);                                         \
            ffma2(a2, q.x, w1r[4*k+2]);                                         \
            ffma2(a3, q.y, w1r[4*k+3]);                                         \
        }                                                                       \
        float2 c = unpack2(fadd2(fadd2(a0, a1), fadd2(a2, a3)));                \
        (cur1) = c.x + c.y;                                                     \
    } while (0)

    #pragma unroll 1
    for (int t = 0; t < T_STEPS; t += 4) {
        const int tn = t + 12;
        if (tn < T_STEPS) {
            PRODUCE(tn);
        } else {
            cp_commit();       // keep outstanding-group count consistent
        }
        cp_wait3();            // group covering steps t..t+3 complete
        __syncwarp();

        // ---- phase 0: 4 GEMMs (independent of recurrent chain) ----
        float c0, c1, c2, c3;
        GEMM((t)     & (DEPTH - 1), c0);
        GEMM((t + 1) & (DEPTH - 1), c1);
        GEMM((t + 2) & (DEPTH - 1), c2);
        GEMM((t + 3) & (DEPTH - 1), c3);

        // ---- phase A: LIF1 chain x4, collect spike masks ----
        unsigned s1m[4];
        #define LIF1(i, cur) do {                                               \
            float r1 = (m1 > 1.0f) ? 1.0f : 0.0f;                               \
            m1 = fmaf(0.9f, m1, (cur)) - r1;                                    \
            s1m[i] = __ballot_sync(0xffffffffu, m1 > 1.0f) & 0x0FFFFFFFu;       \
        } while (0)
        LIF1(0, c0); LIF1(1, c1); LIF1(2, c2); LIF1(3, c3);
        #undef LIF1

        // ---- phase B: all 16 LUT2 loads (independent; latencies overlap) ----
        float lA[4], lB[4], lC[4], lD[4];
        #pragma unroll
        for (int i = 0; i < 4; i++) {
            const unsigned s1 = s1m[i];
            lA[i] = LUT2[0][s1 & 127u][j2];
            lB[i] = LUT2[1][(s1 >> 7) & 127u][j2];
            lC[i] = LUT2[2][(s1 >> 14) & 127u][j2];
            lD[i] = LUT2[3][s1 >> 21][j2];
        }

        // ---- phase C: LIF2 chain x4, collect s2 masks ----
        unsigned s2m[4];
        #pragma unroll
        for (int i = 0; i < 4; i++) {
            float cur2 = b2j + (lA[i] + lB[i]) + (lC[i] + lD[i]);
            float r2 = (m2 > 1.0f) ? 1.0f : 0.0f;
            m2 = fmaf(0.9f, m2, cur2) - r2;
            s2m[i] = __ballot_sync(0xffffffffu, m2 > 1.0f) & 0x3FFFu;
        }

        // ---- phase D: 8 L3 loads (independent) + LIF3 chain x4 + stores ----
        float h0[4], h1[4];
        #pragma unroll
        for (int i = 0; i < 4; i++) {
            h0[i] = L3s[0][s2m[i] & 127u];
            h1[i] = L3s[1][s2m[i] >> 7];
        }
        #pragma unroll
        for (int i = 0; i < 4; i++) {
            float cur3 = b3v + (h0[i] + h1[i]);
            float r3 = (m3 > 1.0f) ? 1.0f : 0.0f;
            m3 = fmaf(0.9f, m3, cur3) - r3;
            if (lane == 0) out[(size_t)(t + i) * BATCH + b] = m3;
        }
    }
    #undef GEMM
    #undef PRODUCE
}

extern "C" void kernel_launch(void* const* d_in, const int* in_sizes, int n_in,
                              void* d_out, int out_size) {
    const float* x  = (const float*)d_in[0];
    const float* W1 = (const float*)d_in[1];
    const float* b1 = (const float*)d_in[2];
    const float* W2 = (const float*)d_in[3];
    const float* b2 = (const float*)d_in[4];
    const float* W3 = (const float*)d_in[5];
    const float* b3 = (const float*)d_in[6];
    snn_all<<<BATCH / 8, 256>>>(x, W1, b1, W2, b2, W3, b3, (float*)d_out);
}

// round 16
// speedup vs baseline: 1.6106x; 1.6106x over previous
#include <cuda_runtime.h>
#include <cstdint>

typedef unsigned long long u64;

#define T_STEPS 256
#define BATCH   8192
#define DEPTH   16           // ring slots (steps); commit granularity = 4 steps
#define NW      10           // warps per CTA (320 threads)

__device__ __forceinline__ void ffma2(u64& acc, u64 a, u64 b) {
    asm("fma.rn.f32x2 %0, %1, %2, %0;" : "+l"(acc) : "l"(a), "l"(b));
}
__device__ __forceinline__ u64 fadd2(u64 a, u64 b) {
    u64 d; asm("add.rn.f32x2 %0, %1, %2;" : "=l"(d) : "l"(a), "l"(b)); return d;
}
__device__ __forceinline__ u64 pack2(float lo, float hi) {
    u64 v; asm("mov.b64 %0, {%1, %2};" : "=l"(v) : "f"(lo), "f"(hi)); return v;
}
__device__ __forceinline__ float2 unpack2(u64 v) {
    float2 r; asm("mov.b64 {%0, %1}, %2;" : "=f"(r.x), "=f"(r.y) : "l"(v)); return r;
}
__device__ __forceinline__ unsigned smem_u32(const void* p) {
    unsigned a;
    asm("{ .reg .u64 t; cvta.to.shared.u64 t, %1; cvt.u32.u64 %0, t; }" : "=r"(a) : "l"(p));
    return a;
}
__device__ __forceinline__ void cp_async16(unsigned dst, const void* src) {
    asm volatile("cp.async.ca.shared.global [%0], [%1], 16;" :: "r"(dst), "l"(src));
}
__device__ __forceinline__ void cp_commit() {
    asm volatile("cp.async.commit_group;" ::: "memory");
}
__device__ __forceinline__ void cp_wait3() {
    asm volatile("cp.async.wait_group 3;" ::: "memory");
}

// Warp = TWO batch elements (lanes 0-15 -> elem b0, lanes 16-31 -> elem b0+1).
// Within a half, lane hj (hj<14 active) owns L1 neurons {hj, hj+14} (both W1
// rows in registers; x read once per element, reused for both rows) and L2
// neuron hj. Spike masks composed from two ballots. W2/W3 via smem LUTs.
// x streamed via per-warp cp.async ring (512B/slot = both elems), 4 steps per
// commit/wait/sync block, 4 GEMMs hoisted ahead of the 4 serial LIF chains.
// NOTE: per-neuron GEMM chain order, LIF, and LUT sum order are bit-identical
// to the proven 344.8us kernel (correctness contract).
__global__ __launch_bounds__(320, 1)
void snn_all(const float* __restrict__ x,
             const float* __restrict__ W1, const float* __restrict__ b1,
             const float* __restrict__ W2, const float* __restrict__ b2,
             const float* __restrict__ W3, const float* __restrict__ b3,
             float* __restrict__ out)
{
    __shared__ __align__(16) u64 xring[NW][DEPTH][2][32];  // 80 KB: 512B/slot (2 elems)
    __shared__ float LUT2[4][128][16];                     // 32 KB (j padded 14->16)
    __shared__ float L3s[2][128];                          // 1 KB

    const int tid = threadIdx.x;

    // ---- build LUTs: LUT2[g][m][j] = sum_{k: m bit k} W2[j, 7g+k] ----
    for (int e = tid; e < 512; e += 320) {
        const int g = e >> 7, m = e & 127;
        #pragma unroll
        for (int j = 0; j < 16; j++) {
            float s = 0.0f;
            if (j < 14) {
                #pragma unroll
                for (int k = 0; k < 7; k++)
                    if (m & (1 << k)) s += W2[j * 28 + 7 * g + k];
            }
            LUT2[g][m][j] = s;
        }
    }
    for (int e = tid; e < 256; e += 320) {
        const int g = e >> 7, m = e & 127;
        float s = 0.0f;
        #pragma unroll
        for (int k = 0; k < 7; k++)
            if (m & (1 << k)) s += W3[7 * g + k];
        L3s[g][m] = s;
    }

    const int lane = tid & 31;
    const int w    = tid >> 5;
    const int half = lane >> 4;          // which element of the pair
    const int hj   = lane & 15;
    const int j    = (hj < 14) ? hj : 13;   // L1/L2 neuron base (dup on 14,15)
    const int b0   = (blockIdx.x * NW + w) * 2;   // even; elems b0, b0+1

    // ---- W1 rows j and j+14 in registers (packed f32x2) ----
    u64 w1a[32], w1b[32];
    {
        const float4* wpa = (const float4*)(W1 + j * 64);
        const float4* wpb = (const float4*)(W1 + (j + 14) * 64);
        #pragma unroll
        for (int k = 0; k < 16; k++) {
            float4 va = wpa[k];
            w1a[2*k]   = pack2(va.x, va.y);
            w1a[2*k+1] = pack2(va.z, va.w);
            float4 vb = wpb[k];
            w1b[2*k]   = pack2(vb.x, vb.y);
            w1b[2*k+1] = pack2(vb.z, vb.w);
        }
    }
    const float b1a = b1[j];
    const float b1b = b1[j + 14];
    const float b2j = b2[j];
    const float b3v = b3[0];

    __syncthreads();   // LUTs ready

    if (b0 >= BATCH) return;   // tail warps idle (BATCH even -> all-or-nothing)

    // ---- cp.async ring: slot = 512B (256B per elem). Lane covers its half's
    // 16B chunk: 1 instruction per slot per warp (512B contiguous in global).
    const float* xg = x + (size_t)(b0 + half) * 64 + hj * 4;
    const size_t tstride = (size_t)BATCH * 64;
    const unsigned ringq = smem_u32(&xring[w][0][0][0]) + (unsigned)(half * 256 + hj * 16);

    #define PRODUCE(tt) do {                                                    \
        _Pragma("unroll")                                                       \
        for (int s_ = 0; s_ < 4; s_++)                                          \
            cp_async16(ringq + (unsigned)((((tt) + s_) & (DEPTH - 1)) * 512),   \
                       xg + (size_t)((tt) + s_) * tstride);                     \
        cp_commit();                                                            \
    } while (0)

    PRODUCE(0); PRODUCE(4); PRODUCE(8);

    float m1a = 0.0f, m1b = 0.0f, m2 = 0.0f, m3 = 0.0f;

    // layer-1 dot products for BOTH owned neurons from ring slot s.
    // Per-neuron chain order is EXACTLY the contractual 4-accumulator order.
    #define GEMM(s, curA, curB) do {                                            \
        const ulonglong2* xv = (const ulonglong2*)&xring[w][(s)][half][0];      \
        u64 a0 = pack2(b1a, 0.0f), a1 = 0ull, a2 = 0ull, a3 = 0ull;             \
        u64 g0 = pack2(b1b, 0.0f), g1 = 0ull, g2 = 0ull, g3 = 0ull;             \
        _Pragma("unroll")                                                       \
        for (int k = 0; k < 8; k++) {                                           \
            ulonglong2 p = xv[2*k];                                             \
            ulonglong2 q = xv[2*k+1];                                           \
            ffma2(a0, p.x, w1a[4*k]);                                           \
            ffma2(a1, p.y, w1a[4*k+1]);                                         \
            ffma2(a2, q.x, w1a[4*k+2]);                                         \
            ffma2(a3, q.y, w1a[4*k+3]);                                         \
            ffma2(g0, p.x, w1b[4*k]);                                           \
            ffma2(g1, p.y, w1b[4*k+1]);                                         \
            ffma2(g2, q.x, w1b[4*k+2]);                                         \
            ffma2(g3, q.y, w1b[4*k+3]);                                         \
        }                                                                       \
        float2 cA = unpack2(fadd2(fadd2(a0, a1), fadd2(a2, a3)));               \
        (curA) = cA.x + cA.y;                                                   \
        float2 cB = unpack2(fadd2(fadd2(g0, g1), fadd2(g2, g3)));               \
        (curB) = cB.x + cB.y;                                                   \
    } while (0)

    #define LIF_STEP(t, curA, curB) do {                                        \
        float r1a = (m1a > 1.0f) ? 1.0f : 0.0f;                                 \
        m1a = fmaf(0.9f, m1a, (curA)) - r1a;                                    \
        float r1b = (m1b > 1.0f) ? 1.0f : 0.0f;                                 \
        m1b = fmaf(0.9f, m1b, (curB)) - r1b;                                    \
        unsigned balA = __ballot_sync(0xffffffffu, m1a > 1.0f);                 \
        unsigned balB = __ballot_sync(0xffffffffu, m1b > 1.0f);                 \
        unsigned mA = (balA & 0x3FFFu) | ((balB & 0x3FFFu) << 14);              \
        unsigned mB = ((balA >> 16) & 0x3FFFu) | (((balB >> 16) & 0x3FFFu) << 14); \
        unsigned s1 = half ? mB : mA;                                           \
        float cur2 = b2j + (LUT2[0][s1 & 127u][j]                               \
                          + LUT2[1][(s1 >> 7) & 127u][j])                       \
                         + (LUT2[2][(s1 >> 14) & 127u][j]                       \
                          + LUT2[3][s1 >> 21][j]);                              \
        float r2 = (m2 > 1.0f) ? 1.0f : 0.0f;                                   \
        m2 = fmaf(0.9f, m2, cur2) - r2;                                         \
        unsigned bal2 = __ballot_sync(0xffffffffu, m2 > 1.0f);                  \
        unsigned s2 = half ? ((bal2 >> 16) & 0x3FFFu) : (bal2 & 0x3FFFu);       \
        float cur3 = b3v + (L3s[0][s2 & 127u] + L3s[1][s2 >> 7]);               \
        float r3 = (m3 > 1.0f) ? 1.0f : 0.0f;                                   \
        m3 = fmaf(0.9f, m3, cur3) - r3;                                         \
        if (hj == 0) out[(size_t)(t) * BATCH + (b0 + half)] = m3;               \
    } while (0)

    #pragma unroll 1
    for (int t = 0; t < T_STEPS; t += 4) {
        const int tn = t + 12;
        if (tn < T_STEPS) {
            PRODUCE(tn);
        } else {
            cp_commit();       // keep outstanding-group count consistent
        }
        cp_wait3();            // group covering steps t..t+3 complete
        __syncwarp();

        // all four GEMMs first — independent of the recurrent chain
        float cA0, cB0, cA1, cB1, cA2, cB2, cA3, cB3;
        GEMM((t)     & (DEPTH - 1), cA0, cB0);
        GEMM((t + 1) & (DEPTH - 1), cA1, cB1);
        GEMM((t + 2) & (DEPTH - 1), cA2, cB2);
        GEMM((t + 3) & (DEPTH - 1), cA3, cB3);

        LIF_STEP(t,     cA0, cB0);
        LIF_STEP(t + 1, cA1, cB1);
        LIF_STEP(t + 2, cA2, cB2);
        LIF_STEP(t + 3, cA3, cB3);
    }
    #undef GEMM
    #undef LIF_STEP
    #undef PRODUCE
}

extern "C" void kernel_launch(void* const* d_in, const int* in_sizes, int n_in,
                              void* d_out, int out_size) {
    const float* x  = (const float*)d_in[0];
    const float* W1 = (const float*)d_in[1];
    const float* b1 = (const float*)d_in[2];
    const float* W2 = (const float*)d_in[3];
    const float* b2 = (const float*)d_in[4];
    const float* W3 = (const float*)d_in[5];
    const float* b3 = (const float*)d_in[6];
    const int ctas = (BATCH / 2 + NW - 1) / NW;   // 410
    snn_all<<<ctas, NW * 32>>>(x, W1, b1, W2, b2, W3, b3, (float*)d_out);
}